// round 10
// baseline (speedup 1.0000x reference)
#include <cuda_runtime.h>
#include <cuda_bf16.h>

#define CLS 128
#define NCNT (5 * CLS)
#define ILP 4
#define GRID 1184            // 148 SMs x 8 blocks: one persistent wave
#define TPB 256
#define NWARPS (GRID * (TPB / 32))   // 9472 warps

// [0:128)   diag[c]   : true==pred==c           (TP)
// [128:256) colA[c]   : true=c, pred=0          (conf[c,0])
// [256:384) colB[c]   : true=c, pred=1          (conf[c,1])
// [384:512) rowA[c]   : true=0, pred=c          (conf[0,c])
// [512:640) rowB[c]   : true=1, pred=c          (conf[1,c])
__device__ int g_cnt[NCNT];            // zero-initialized; self-cleaned each launch
__device__ unsigned g_done;            // zero-initialized; self-cleaned each launch

__device__ __forceinline__ unsigned f2key(float f) {
    unsigned u = __float_as_uint(f);
    return (u & 0x80000000u) ? ~u : (u | 0x80000000u);  // monotone: key order == float order
}

__device__ __forceinline__ void bump(int* s_cnt, int t, int p) {
    if (t == p)  atomicAdd(&s_cnt[t], 1);
    if (p == 0)  atomicAdd(&s_cnt[CLS     + t], 1);
    if (p == 1)  atomicAdd(&s_cnt[2 * CLS + t], 1);
    if (t == 0)  atomicAdd(&s_cnt[3 * CLS + p], 1);
    if (t == 1)  atomicAdd(&s_cnt[4 * CLS + p], 1);
}

__device__ __forceinline__ int warp_argmax(float4 v, int lane) {
    float bv = v.x; int bi = lane * 4;
    if (v.y > bv) { bv = v.y; bi = lane * 4 + 1; }
    if (v.z > bv) { bv = v.z; bi = lane * 4 + 2; }
    if (v.w > bv) { bv = v.w; bi = lane * 4 + 3; }
    unsigned key = f2key(bv);
    unsigned m   = __reduce_max_sync(0xffffffffu, key);
    // first-occurrence argmax: min index among lanes holding the max
    return (int)__reduce_min_sync(0xffffffffu, (key == m) ? (unsigned)bi : 0x7fffffffu);
}

__global__ void __launch_bounds__(TPB) f1_kernel(const float* __restrict__ y_pred,
                                                 const int* __restrict__ y_true,
                                                 int n, int tstride,
                                                 float* __restrict__ out) {
    __shared__ int s_cnt[NCNT];
    __shared__ unsigned s_last;
    for (int i = threadIdx.x; i < NCNT; i += TPB) s_cnt[i] = 0;
    __syncthreads();

    const int lane  = threadIdx.x & 31;
    const int warp  = threadIdx.x >> 5;
    const int gwarp = blockIdx.x * (TPB >> 5) + warp;

    // contiguous slab per warp: warp streams sequentially through ~n/NWARPS rows
    int beg = (int)((long long)gwarp      * n / NWARPS);
    int end = (int)((long long)(gwarp + 1) * n / NWARPS);

    int r0 = beg;
    for (; r0 + ILP <= end; r0 += ILP) {
        const float4* p = reinterpret_cast<const float4*>(y_pred) + (size_t)r0 * (CLS / 4) + lane;
        float4 v[ILP];
        #pragma unroll
        for (int k = 0; k < ILP; k++)
            v[k] = __ldcs(p + k * (CLS / 4));      // 4 rows x 512B, sequential within slab

        // hoist y_true load: overlaps its latency with the argmax reductions
        int t = (lane < ILP) ? y_true[(r0 + lane) * tstride] : 0;

        int pr[ILP];
        #pragma unroll
        for (int k = 0; k < ILP; k++)
            pr[k] = warp_argmax(v[k], lane);

        if (lane < ILP)
            bump(s_cnt, t, pr[lane]);
    }
    // slab remainder (0..3 rows)
    for (; r0 < end; r0++) {
        float4 v = __ldcs(reinterpret_cast<const float4*>(y_pred + (size_t)r0 * CLS) + lane);
        int p = warp_argmax(v, lane);
        if (lane == 0) bump(s_cnt, y_true[r0 * tstride], p);
    }

    __syncthreads();
    for (int i = threadIdx.x; i < NCNT; i += TPB) {
        int c = s_cnt[i];
        if (c) atomicAdd(&g_cnt[i], c);
    }

    // ---- last-block-done: fused finalize + self-clean for next graph replay ----
    __threadfence();
    if (threadIdx.x == 0)
        s_last = (atomicAdd(&g_done, 1u) == (unsigned)gridDim.x - 1u);
    __syncthreads();
    if (!s_last) return;

    __threadfence();                       // acquire: see all blocks' g_cnt atomics
    __shared__ float s[CLS];
    if (threadIdx.x < CLS) {
        const int c = threadIdx.x;
        const float eps = 1e-12f;
        float TP = (float)g_cnt[c];
        float FP = 127.0f * (float)g_cnt[2 * CLS + c] + (float)g_cnt[CLS + c];
        float FN = 127.0f * (float)g_cnt[4 * CLS + c] + (float)g_cnt[3 * CLS + c];
        float sens = TP / (TP + FN + eps);
        float prec = TP / (TP + FP + eps);
        s[c] = 2.0f * (prec * sens / (prec + sens + eps));
    }
    __syncthreads();
    #pragma unroll
    for (int off = 64; off; off >>= 1) {
        if (threadIdx.x < off) s[threadIdx.x] += s[threadIdx.x + off];
        __syncthreads();
    }
    if (threadIdx.x == 0) {
        out[0] = s[0] / (float)CLS;
        g_done = 0u;                       // reset for next replay
    }
    for (int i = threadIdx.x; i < NCNT; i += TPB) g_cnt[i] = 0;   // re-zero counters
}

extern "C" void kernel_launch(void* const* d_in, const int* in_sizes, int n_in,
                              void* d_out, int out_size) {
    const float* y_pred = (const float*)d_in[0];
    const int*   y_true = (const int*)d_in[1];

    int n = in_sizes[0] / CLS;            // rows, derived from y_pred (unambiguous)
    int tstride = in_sizes[1] / n;        // 1 if int32, 2 if int64 passed as words
    if (tstride < 1) tstride = 1;

    f1_kernel<<<GRID, TPB>>>(y_pred, y_true, n, tstride, (float*)d_out);
}

// round 11
// speedup vs baseline: 1.0902x; 1.0902x over previous
#include <cuda_runtime.h>
#include <cuda_bf16.h>

#define CLS 128
#define NCNT (5 * CLS)
#define ILP 4
#define GRID 2048
#define TPB 256

// [0:128)   diag[c]   : true==pred==c           (TP)
// [128:256) colA[c]   : true=c, pred=0          (conf[c,0])
// [256:384) colB[c]   : true=c, pred=1          (conf[c,1])
// [384:512) rowA[c]   : true=0, pred=c          (conf[0,c])
// [512:640) rowB[c]   : true=1, pred=c          (conf[1,c])
__device__ int g_cnt[NCNT];            // zero-initialized; self-cleaned each launch
__device__ unsigned g_done;            // zero-initialized; self-cleaned each launch

__device__ __forceinline__ unsigned f2key(float f) {
    unsigned u = __float_as_uint(f);
    return (u & 0x80000000u) ? ~u : (u | 0x80000000u);  // monotone: key order == float order
}

__device__ __forceinline__ void bump(int* s_cnt, int t, int p) {
    if (t == p)  atomicAdd(&s_cnt[t], 1);
    if (p == 0)  atomicAdd(&s_cnt[CLS     + t], 1);
    if (p == 1)  atomicAdd(&s_cnt[2 * CLS + t], 1);
    if (t == 0)  atomicAdd(&s_cnt[3 * CLS + p], 1);
    if (t == 1)  atomicAdd(&s_cnt[4 * CLS + p], 1);
}

__device__ __forceinline__ int warp_argmax(float4 v, int lane) {
    float bv = v.x; int bi = lane * 4;
    if (v.y > bv) { bv = v.y; bi = lane * 4 + 1; }
    if (v.z > bv) { bv = v.z; bi = lane * 4 + 2; }
    if (v.w > bv) { bv = v.w; bi = lane * 4 + 3; }
    unsigned key = f2key(bv);
    unsigned m   = __reduce_max_sync(0xffffffffu, key);
    // first-occurrence argmax: min index among lanes holding the max
    return (int)__reduce_min_sync(0xffffffffu, (key == m) ? (unsigned)bi : 0x7fffffffu);
}

__global__ void __launch_bounds__(TPB) f1_kernel(const float* __restrict__ y_pred,
                                                 const int* __restrict__ y_true,
                                                 int n, int tstride,
                                                 float* __restrict__ out) {
    __shared__ int s_cnt[NCNT];
    __shared__ unsigned s_last;
    for (int i = threadIdx.x; i < NCNT; i += TPB) s_cnt[i] = 0;
    __syncthreads();

    const int lane   = threadIdx.x & 31;
    const int warp   = threadIdx.x >> 5;
    const int gwarp  = blockIdx.x * (TPB >> 5) + warp;
    const int step   = GRID * (TPB >> 5) * ILP;    // interleaved grid-stride (R6 winner)

    int r0 = gwarp * ILP;
    for (; r0 + ILP <= n; r0 += step) {
        const float4* p = reinterpret_cast<const float4*>(y_pred) + (size_t)r0 * (CLS / 4) + lane;
        float4 v[ILP];
        #pragma unroll
        for (int k = 0; k < ILP; k++)
            v[k] = __ldcs(p + k * (CLS / 4));      // 4 rows x 512B contiguous, MLP=4

        // hoist y_true load: overlaps its latency with the argmax reductions
        int t = (lane < ILP) ? y_true[(r0 + lane) * tstride] : 0;

        int pr[ILP];
        #pragma unroll
        for (int k = 0; k < ILP; k++)
            pr[k] = warp_argmax(v[k], lane);

        if (lane < ILP)
            bump(s_cnt, t, pr[lane]);
    }
    // remainder (never taken for n = 2^20, kept for generality)
    for (; r0 < n; r0++) {
        float4 v = __ldcs(reinterpret_cast<const float4*>(y_pred + (size_t)r0 * CLS) + lane);
        int p = warp_argmax(v, lane);
        if (lane == 0) bump(s_cnt, y_true[r0 * tstride], p);
    }

    __syncthreads();
    for (int i = threadIdx.x; i < NCNT; i += TPB) {
        int c = s_cnt[i];
        if (c) atomicAdd(&g_cnt[i], c);
    }

    // ---- last-block-done: fused finalize + self-clean for next graph replay ----
    __threadfence();
    if (threadIdx.x == 0)
        s_last = (atomicAdd(&g_done, 1u) == (unsigned)gridDim.x - 1u);
    __syncthreads();
    if (!s_last) return;

    __threadfence();                       // acquire: see all blocks' g_cnt atomics
    __shared__ float s[CLS];
    if (threadIdx.x < CLS) {
        const int c = threadIdx.x;
        const float eps = 1e-12f;
        float TP = (float)g_cnt[c];
        float FP = 127.0f * (float)g_cnt[2 * CLS + c] + (float)g_cnt[CLS + c];
        float FN = 127.0f * (float)g_cnt[4 * CLS + c] + (float)g_cnt[3 * CLS + c];
        float sens = TP / (TP + FN + eps);
        float prec = TP / (TP + FP + eps);
        s[c] = 2.0f * (prec * sens / (prec + sens + eps));
    }
    __syncthreads();
    #pragma unroll
    for (int off = 64; off; off >>= 1) {
        if (threadIdx.x < off) s[threadIdx.x] += s[threadIdx.x + off];
        __syncthreads();
    }
    if (threadIdx.x == 0) {
        out[0] = s[0] / (float)CLS;
        g_done = 0u;                       // reset for next replay
    }
    for (int i = threadIdx.x; i < NCNT; i += TPB) g_cnt[i] = 0;   // re-zero counters
}

extern "C" void kernel_launch(void* const* d_in, const int* in_sizes, int n_in,
                              void* d_out, int out_size) {
    const float* y_pred = (const float*)d_in[0];
    const int*   y_true = (const int*)d_in[1];

    int n = in_sizes[0] / CLS;            // rows, derived from y_pred (unambiguous)
    int tstride = in_sizes[1] / n;        // 1 if int32, 2 if int64 passed as words
    if (tstride < 1) tstride = 1;

    f1_kernel<<<GRID, TPB>>>(y_pred, y_true, n, tstride, (float*)d_out);
}

// round 13
// speedup vs baseline: 1.1214x; 1.0287x over previous
#include <cuda_runtime.h>
#include <cuda_bf16.h>

#define CLS 128
#define NCNT (5 * CLS)
#define ILP 4
#define GRID 2048
#define TPB 256
#define CHUNK 128            // rows per stolen chunk (= 8 warps * 4 ILP * 4 iter)

// [0:128)   diag[c]   : true==pred==c           (TP)
// [128:256) colA[c]   : true=c, pred=0          (conf[c,0])
// [256:384) colB[c]   : true=c, pred=1          (conf[c,1])
// [384:512) rowA[c]   : true=0, pred=c          (conf[0,c])
// [512:640) rowB[c]   : true=1, pred=c          (conf[1,c])
__device__ int g_cnt[NCNT];            // zero-initialized; self-cleaned each launch
__device__ unsigned g_done;            // zero-initialized; self-cleaned each launch
__device__ unsigned g_tick;            // work-stealing ticket; self-cleaned each launch

__device__ __forceinline__ unsigned f2key(float f) {
    unsigned u = __float_as_uint(f);
    return (u & 0x80000000u) ? ~u : (u | 0x80000000u);  // monotone: key order == float order
}

__device__ __forceinline__ void bump(int* s_cnt, int t, int p) {
    if (t == p)  atomicAdd(&s_cnt[t], 1);
    if (p == 0)  atomicAdd(&s_cnt[CLS     + t], 1);
    if (p == 1)  atomicAdd(&s_cnt[2 * CLS + t], 1);
    if (t == 0)  atomicAdd(&s_cnt[3 * CLS + p], 1);
    if (t == 1)  atomicAdd(&s_cnt[4 * CLS + p], 1);
}

__device__ __forceinline__ int warp_argmax(float4 v, int lane) {
    float bv = v.x; int bi = lane * 4;
    if (v.y > bv) { bv = v.y; bi = lane * 4 + 1; }
    if (v.z > bv) { bv = v.z; bi = lane * 4 + 2; }
    if (v.w > bv) { bv = v.w; bi = lane * 4 + 3; }
    unsigned key = f2key(bv);
    unsigned m   = __reduce_max_sync(0xffffffffu, key);
    // first-occurrence argmax: min index among lanes holding the max
    return (int)__reduce_min_sync(0xffffffffu, (key == m) ? (unsigned)bi : 0x7fffffffu);
}

__global__ void __launch_bounds__(TPB) f1_kernel(const float* __restrict__ y_pred,
                                                 const int* __restrict__ y_true,
                                                 int n, int tstride,
                                                 float* __restrict__ out) {
    __shared__ int s_cnt[NCNT];
    __shared__ unsigned s_last;
    __shared__ unsigned s_chunk;
    for (int i = threadIdx.x; i < NCNT; i += TPB) s_cnt[i] = 0;
    __syncthreads();

    const int lane = threadIdx.x & 31;
    const int warp = threadIdx.x >> 5;
    const unsigned nchunks = ((unsigned)n + CHUNK - 1) / CHUNK;

    for (;;) {
        // one thread per block grabs the next chunk of 128 rows
        if (threadIdx.x == 0) s_chunk = atomicAdd(&g_tick, 1u);
        __syncthreads();
        unsigned ck = s_chunk;
        if (ck >= nchunks) break;

        int base = (int)ck * CHUNK;
        int lim  = min(base + CHUNK, n);

        // warps interleave within the chunk: warp w -> rows base + w*ILP + i*32
        for (int r0 = base + warp * ILP; r0 + ILP <= lim; r0 += (TPB >> 5) * ILP) {
            const float4* p = reinterpret_cast<const float4*>(y_pred) + (size_t)r0 * (CLS / 4) + lane;
            float4 v[ILP];
            #pragma unroll
            for (int k = 0; k < ILP; k++)
                v[k] = __ldcs(p + k * (CLS / 4));  // 4 rows x 512B contiguous, MLP=4

            int t = (lane < ILP) ? y_true[(r0 + lane) * tstride] : 0;

            int pr[ILP];
            #pragma unroll
            for (int k = 0; k < ILP; k++)
                pr[k] = warp_argmax(v[k], lane);

            if (lane < ILP)
                bump(s_cnt, t, pr[lane]);
        }
        // chunk remainder rows (only possible in the very last chunk)
        if (ck == nchunks - 1) {
            int rem = base + (CHUNK / (ILP * (TPB >> 5))) * (ILP * (TPB >> 5));
            int start = max(base, lim - (lim - base) % ILP);
            // handle rows not covered by full ILP tiles, warp 0 only
            if (warp == 0) {
                for (int r = start; r < lim; r++) {
                    float4 v = __ldcs(reinterpret_cast<const float4*>(y_pred + (size_t)r * CLS) + lane);
                    int p = warp_argmax(v, lane);
                    if (lane == 0) bump(s_cnt, y_true[r * tstride], p);
                }
            }
            (void)rem;
        }
        __syncthreads();
    }

    for (int i = threadIdx.x; i < NCNT; i += TPB) {
        int c = s_cnt[i];
        if (c) atomicAdd(&g_cnt[i], c);
    }

    // ---- last-block-done: fused finalize + self-clean for next graph replay ----
    __threadfence();
    if (threadIdx.x == 0)
        s_last = (atomicAdd(&g_done, 1u) == (unsigned)gridDim.x - 1u);
    __syncthreads();
    if (!s_last) return;

    __threadfence();                       // acquire: see all blocks' g_cnt atomics
    __shared__ float s[CLS];
    if (threadIdx.x < CLS) {
        const int c = threadIdx.x;
        const float eps = 1e-12f;
        float TP = (float)g_cnt[c];
        float FP = 127.0f * (float)g_cnt[2 * CLS + c] + (float)g_cnt[CLS + c];
        float FN = 127.0f * (float)g_cnt[4 * CLS + c] + (float)g_cnt[3 * CLS + c];
        float sens = TP / (TP + FN + eps);
        float prec = TP / (TP + FP + eps);
        s[c] = 2.0f * (prec * sens / (prec + sens + eps));
    }
    __syncthreads();
    #pragma unroll
    for (int off = 64; off; off >>= 1) {
        if (threadIdx.x < off) s[threadIdx.x] += s[threadIdx.x + off];
        __syncthreads();
    }
    if (threadIdx.x == 0) {
        out[0] = s[0] / (float)CLS;
        g_done = 0u;                       // reset for next replay
        g_tick = 0u;                       // reset ticket for next replay
    }
    for (int i = threadIdx.x; i < NCNT; i += TPB) g_cnt[i] = 0;   // re-zero counters
}

extern "C" void kernel_launch(void* const* d_in, const int* in_sizes, int n_in,
                              void* d_out, int out_size) {
    const float* y_pred = (const float*)d_in[0];
    const int*   y_true = (const int*)d_in[1];

    int n = in_sizes[0] / CLS;            // rows, derived from y_pred (unambiguous)
    int tstride = in_sizes[1] / n;        // 1 if int32, 2 if int64 passed as words
    if (tstride < 1) tstride = 1;

    f1_kernel<<<GRID, TPB>>>(y_pred, y_true, n, tstride, (float*)d_out);
}